// round 11
// baseline (speedup 1.0000x reference)
#include <cuda_runtime.h>
#include <cuda_bf16.h>
#include <cstdint>

// Problem constants (fixed shapes per reference)
#define N1 8
#define N2 8
#define PN 1024
#define DD 768
#define PHH 32
#define PWW 32
#define HH 512
#define WW 512

#define FLT_BIG 3.402823466e38f

// GEMM tiling: 128x256 CTA tile, 8 warps (2 x 4), 64x64 warp tile, BK=32
#define BM 128
#define BN 256
#define BK 32
#define NCHUNK (DD / BK)   // 24
#define SPAD 40            // smem row stride in bf16 (32 data + 8 pad), 80B (16B-mult)

// dynamic smem layout (bytes)
#define OF_A 0                       // A[2][128][40] bf16 = 2*10240
#define OF_B 20480                   // B[2][256][40] bf16 = 2*20480
#define ASTRIDE 10240
#define BSTRIDE 20480
#define SMEM_TOTAL (20480 + 40960)   // 61440

// -------- scratch (static device globals; no allocations allowed) ----------
__device__ __align__(256) __nv_bfloat16 g_fnh[N1 * PN * DD];  // normalized feats (bf16)
__device__ __align__(256) __nv_bfloat16 g_gnh[N2 * PN * DD];  // normalized nfeats (bf16)
__device__ float    g_fa2[N1 * PN];
__device__ float    g_gb2[N2 * PN];
__device__ unsigned g_minenc[N1 * N2 * PN];    // order-encoded min d2 over q
__device__ float    g_spatch[N1 * N2 * PN];
__device__ float    g_maxp[N1 * N2];
__device__ float    g_sp[N1 * PN];

// ---------------- helpers ----------------
__device__ __forceinline__ unsigned enc_f(float f) {
    unsigned u = __float_as_uint(f);
    return (u & 0x80000000u) ? ~u : (u | 0x80000000u);
}
__device__ __forceinline__ float dec_f(unsigned e) {
    unsigned u = (e & 0x80000000u) ? (e ^ 0x80000000u) : ~e;
    return __uint_as_float(u);
}
__device__ __forceinline__ uint32_t smem_u32(const void* p) {
    uint32_t a;
    asm("{ .reg .u64 t; cvta.to.shared.u64 t, %1; cvt.u32.u64 %0, t; }" : "=r"(a) : "l"(p));
    return a;
}
__device__ __forceinline__ void cp16(uint32_t dst, const void* src) {
    asm volatile("cp.async.cg.shared.global [%0], [%1], 16;" :: "r"(dst), "l"(src) : "memory");
}
__device__ __forceinline__ void cp_commit() {
    asm volatile("cp.async.commit_group;" ::: "memory");
}
__device__ __forceinline__ void cp_wait1() {
    asm volatile("cp.async.wait_group 1;" ::: "memory");
}
__device__ __forceinline__ void cp_wait0() {
    asm volatile("cp.async.wait_group 0;" ::: "memory");
}
__device__ __forceinline__ void mma_bf16(float& c0, float& c1, float& c2, float& c3,
                                         unsigned a0, unsigned a1, unsigned a2, unsigned a3,
                                         unsigned b0, unsigned b1) {
    asm volatile(
        "mma.sync.aligned.m16n8k16.row.col.f32.bf16.bf16.f32 "
        "{%0,%1,%2,%3}, {%4,%5,%6,%7}, {%8,%9}, {%0,%1,%2,%3};\n"
        : "+f"(c0), "+f"(c1), "+f"(c2), "+f"(c3)
        : "r"(a0), "r"(a1), "r"(a2), "r"(a3), "r"(b0), "r"(b1));
}

// ---------------- kernel 1: row-normalize -> bf16 + sum-of-squares ----------
__global__ void normalize_kernel(const float* __restrict__ in, int which) {
    int row = blockIdx.x;
    const float* x = in + (size_t)row * DD;
    __nv_bfloat16* y = (which ? g_gnh : g_fnh) + (size_t)row * DD;
    float* sq = (which ? g_gb2 : g_fa2);

    __shared__ float red[256];
    int t = threadIdx.x;

    float s = 0.f;
    for (int i = t; i < DD; i += 256) { float v = x[i]; s += v * v; }
    red[t] = s; __syncthreads();
    for (int o = 128; o > 0; o >>= 1) { if (t < o) red[t] += red[t + o]; __syncthreads(); }
    float nrm = sqrtf(red[0]);
    __syncthreads();

    float s2 = 0.f;
    for (int i = t; i < DD; i += 256) {
        float v = x[i] / nrm;
        y[i] = __float2bfloat16_rn(v);
        s2 += v * v;
    }
    red[t] = s2; __syncthreads();
    for (int o = 128; o > 0; o >>= 1) { if (t < o) red[t] += red[t + o]; __syncthreads(); }
    if (t == 0) sq[row] = red[0];
}

// ---------------- kernel 2: init min buffer ----------------
__global__ void init_min_kernel() {
    int i = blockIdx.x * blockDim.x + threadIdx.x;
    if (i < N1 * N2 * PN) g_minenc[i] = 0xFFFFFFFFu;
}

// ---------------- kernel 3: bf16 MMA GEMM (64x64 warp tile) + min epilogue --
// C[p,q] = f_n[p].g_m[q]; per-p min over q of (gb2[q] - 2C) -> atomicMin.
// cp.async double-buffered smem pipeline; 8 warps, warp tile 64x64 via
// 4x8 m16n8k16 bf16 mma.sync; padded rows (SPAD=40) -> conflict-free frags.
__global__ __launch_bounds__(256) void gemm_min_kernel() {
    extern __shared__ char smem[];
    const uint32_t sb = smem_u32(smem);

    const int t = threadIdx.x;
    const int lane = t & 31, w = t >> 5;
    const int wm = w >> 2;      // 0..1 -> 64 rows each
    const int wn = w & 3;       // 0..3 -> 64 cols each
    const int grp = lane >> 2;  // 0..7
    const int qd = lane & 3;    // 0..3

    const int nI = blockIdx.z >> 3, mI = blockIdx.z & 7;
    const int p0 = blockIdx.y * BM, q0 = blockIdx.x * BN;

    const __nv_bfloat16* __restrict__ Fp = g_fnh + ((size_t)nI * PN + p0) * DD;
    const __nv_bfloat16* __restrict__ Gp = g_gnh + ((size_t)mI * PN + q0) * DD;

    // loader mapping (per chunk of BK=32):
    //  A: 2 thr/row (128 rows), 16 elems (2 x 16B) each
    //  B: 1 thr/row (256 rows), 32 elems (4 x 16B) each
    const int ra = t >> 1, hf = t & 1;
    const char* gA = (const char*)(Fp + (size_t)ra * DD) + hf * 32;  // + c*64 bytes
    const char* gB = (const char*)(Gp + (size_t)t * DD);             // + c*64 bytes
    const uint32_t sA = sb + OF_A + ra * (SPAD * 2) + hf * 32;       // + buf*ASTRIDE
    const uint32_t sBb = sb + OF_B + t * (SPAD * 2);                 // + buf*BSTRIDE

    float acc[4][8][4];
#pragma unroll
    for (int i = 0; i < 4; i++)
#pragma unroll
        for (int j = 0; j < 8; j++)
#pragma unroll
            for (int c = 0; c < 4; c++) acc[i][j][c] = 0.f;

    // issue chunk c into buffer c&1
#define ISSUE(c)                                                        \
    do {                                                                \
        const int _b = (c) & 1;                                         \
        const uint32_t _sa = sA + _b * ASTRIDE;                         \
        const uint32_t _sb2 = sBb + _b * BSTRIDE;                       \
        const char* _ga = gA + (c) * 64;                                \
        const char* _gb = gB + (c) * 64;                                \
        cp16(_sa, _ga); cp16(_sa + 16, _ga + 16);                       \
        cp16(_sb2, _gb); cp16(_sb2 + 16, _gb + 16);                     \
        cp16(_sb2 + 32, _gb + 32); cp16(_sb2 + 48, _gb + 48);           \
        cp_commit();                                                    \
    } while (0)

    ISSUE(0);
    ISSUE(1);

    for (int c = 0; c < NCHUNK; c++) {
        if (c >= NCHUNK - 2) cp_wait0(); else cp_wait1();
        __syncthreads();

        const int b = c & 1;
        const __nv_bfloat16* Ab = (const __nv_bfloat16*)(smem + OF_A + b * ASTRIDE);
        const __nv_bfloat16* Bb = (const __nv_bfloat16*)(smem + OF_B + b * BSTRIDE);

#pragma unroll
        for (int kk = 0; kk < BK; kk += 16) {
            unsigned bf[8][2];
#pragma unroll
            for (int j = 0; j < 8; j++) {
                const int col = wn * 64 + j * 8 + grp;
                bf[j][0] = *(const unsigned*)&Bb[col * SPAD + kk + qd * 2];
                bf[j][1] = *(const unsigned*)&Bb[col * SPAD + kk + qd * 2 + 8];
            }
#pragma unroll
            for (int i = 0; i < 4; i++) {
                const int row = wm * 64 + i * 16 + grp;
                const unsigned a0 = *(const unsigned*)&Ab[row * SPAD + kk + qd * 2];
                const unsigned a1 = *(const unsigned*)&Ab[(row + 8) * SPAD + kk + qd * 2];
                const unsigned a2 = *(const unsigned*)&Ab[row * SPAD + kk + qd * 2 + 8];
                const unsigned a3 = *(const unsigned*)&Ab[(row + 8) * SPAD + kk + qd * 2 + 8];
#pragma unroll
                for (int j = 0; j < 8; j++)
                    mma_bf16(acc[i][j][0], acc[i][j][1], acc[i][j][2], acc[i][j][3],
                             a0, a1, a2, a3, bf[j][0], bf[j][1]);
            }
        }
        __syncthreads();
        if (c + 2 < NCHUNK) ISSUE(c + 2);
    }
#undef ISSUE

    // ---------------- epilogue: min over q of (gb2[q] - 2*C[p,q]) ----------
    const float* __restrict__ gb2p = g_gb2 + mI * PN + q0;
    float gbv[8][2];
#pragma unroll
    for (int j = 0; j < 8; j++) {
        const int cidx = wn * 64 + j * 8 + qd * 2;
        gbv[j][0] = gb2p[cidx];
        gbv[j][1] = gb2p[cidx + 1];
    }

    float (*red)[4] = (float (*)[4])smem;  // [128 rows][4 wn], aliases buf A0 (done)

#pragma unroll
    for (int i = 0; i < 4; i++) {
        float mn_lo = FLT_BIG, mn_hi = FLT_BIG;
#pragma unroll
        for (int j = 0; j < 8; j++) {
            mn_lo = fminf(mn_lo, gbv[j][0] - 2.f * acc[i][j][0]);
            mn_lo = fminf(mn_lo, gbv[j][1] - 2.f * acc[i][j][1]);
            mn_hi = fminf(mn_hi, gbv[j][0] - 2.f * acc[i][j][2]);
            mn_hi = fminf(mn_hi, gbv[j][1] - 2.f * acc[i][j][3]);
        }
#pragma unroll
        for (int o = 1; o < 4; o <<= 1) {
            mn_lo = fminf(mn_lo, __shfl_xor_sync(0xFFFFFFFFu, mn_lo, o));
            mn_hi = fminf(mn_hi, __shfl_xor_sync(0xFFFFFFFFu, mn_hi, o));
        }
        if (qd == 0) {
            red[wm * 64 + i * 16 + grp][wn]     = mn_lo;
            red[wm * 64 + i * 16 + grp + 8][wn] = mn_hi;
        }
    }
    __syncthreads();

    if (t < BM) {
        const float mn = fminf(fminf(red[t][0], red[t][1]), fminf(red[t][2], red[t][3]));
        const float d2 = g_fa2[nI * PN + p0 + t] + mn;
        atomicMin(&g_minenc[((nI << 3) + mI) * PN + p0 + t], enc_f(d2));
    }
}

// ---------------- kernel 4: scores_patch + max over p ----------------
__global__ void patch_kernel() {
    const int nm = blockIdx.x;
    __shared__ float red[256];
    const int t = threadIdx.x;
    float mx = 0.f;
    for (int p = t; p < PN; p += 256) {
        const float d2 = dec_f(g_minenc[nm * PN + p]);
        const float s = 0.5f * sqrtf(fmaxf(d2, 0.f));
        g_spatch[nm * PN + p] = s;
        mx = fmaxf(mx, s);
    }
    red[t] = mx; __syncthreads();
    for (int o = 128; o > 0; o >>= 1) { if (t < o) red[t] = fmaxf(red[t], red[t + o]); __syncthreads(); }
    if (t == 0) g_maxp[nm] = red[0];
}

// ---------------- kernel 5: mean over m (sp) + scores ----------------
__global__ void reduce_kernel(float* __restrict__ out) {
    const int idx = blockIdx.x * blockDim.x + threadIdx.x;
    if (idx >= N1 * PN) return;
    const int n = idx / PN;
    const int p = idx - n * PN;
    float s = 0.f;
#pragma unroll
    for (int m = 0; m < N2; m++) s += g_spatch[((n << 3) + m) * PN + p];
    g_sp[idx] = s * (1.0f / N2);
    if (idx < N1) {
        float sc = 0.f;
#pragma unroll
        for (int m = 0; m < N2; m++) sc += g_maxp[(idx << 3) + m];
        out[idx] = sc * (1.0f / N2);
    }
}

// ---------------- kernel 6: bilinear resize 32x32 -> 512x512 ----------------
__global__ void bilinear_kernel(float* __restrict__ out) {
    const int gid = blockIdx.x * blockDim.x + threadIdx.x;
    if (gid >= N1 * HH * WW) return;
    const int x = gid % WW;
    const int y = (gid / WW) % HH;
    const int n = gid / (WW * HH);

    const float sy = (y + 0.5f) * ((float)PHH / (float)HH) - 0.5f;
    const float sx = (x + 0.5f) * ((float)PWW / (float)WW) - 0.5f;
    const float y0f = floorf(sy), x0f = floorf(sx);
    const float wy = sy - y0f, wx = sx - x0f;
    const int y0 = min(max((int)y0f, 0), PHH - 1);
    const int y1 = min(max((int)y0f + 1, 0), PHH - 1);
    const int x0 = min(max((int)x0f, 0), PWW - 1);
    const int x1 = min(max((int)x0f + 1, 0), PWW - 1);

    const float* sp = g_sp + n * PN;
    const float v00 = sp[y0 * PWW + x0];
    const float v01 = sp[y0 * PWW + x1];
    const float v10 = sp[y1 * PWW + x0];
    const float v11 = sp[y1 * PWW + x1];
    const float top = v00 * (1.f - wx) + v01 * wx;
    const float bot = v10 * (1.f - wx) + v11 * wx;
    out[N1 + gid] = top * (1.f - wy) + bot * wy;
}

// ---------------- launch ----------------
extern "C" void kernel_launch(void* const* d_in, const int* in_sizes, int n_in,
                              void* d_out, int out_size) {
    const float* feats  = (const float*)d_in[0];
    const float* nfeats = (const float*)d_in[1];
    float* out = (float*)d_out;
    (void)in_sizes; (void)n_in; (void)out_size;

    cudaFuncSetAttribute(gemm_min_kernel,
                         cudaFuncAttributeMaxDynamicSharedMemorySize, SMEM_TOTAL);

    normalize_kernel<<<N1 * PN, 256>>>(feats, 0);
    normalize_kernel<<<N2 * PN, 256>>>(nfeats, 1);
    init_min_kernel<<<(N1 * N2 * PN + 255) / 256, 256>>>();
    gemm_min_kernel<<<dim3(PN / BN, PN / BM, N1 * N2), 256, SMEM_TOTAL>>>();
    patch_kernel<<<N1 * N2, 256>>>();
    reduce_kernel<<<(N1 * PN + 255) / 256, 256>>>(out);
    bilinear_kernel<<<(N1 * HH * WW + 255) / 256, 256>>>(out);
}

// round 14
// speedup vs baseline: 2.0713x; 2.0713x over previous
#include <cuda_runtime.h>
#include <cuda_bf16.h>
#include <cstdint>

// Problem constants (fixed shapes per reference)
#define N1 8
#define N2 8
#define PN 1024
#define DD 768
#define PHH 32
#define PWW 32
#define HH 512
#define WW 512

#define FLT_BIG 3.402823466e38f

// GEMM tiling: 128x128 CTA tile, 8 warps (2 x 4), 64x32 warp tile, BK=32
// 3-stage cp.async pipeline, ldmatrix fragment loads.
#define BM 128
#define BN 128
#define BK 32
#define NCHUNK (DD / BK)    // 24
#define ROWB 80             // smem row stride bytes (32 bf16 = 64B data + 16B pad)
#define STAGE_BYTES 20480   // A(128*80) + B(128*80)
#define OF_Bm 10240         // B offset within a stage
#define SMEM_TOTAL (3 * STAGE_BYTES)   // 61440

// -------- scratch (static device globals; no allocations allowed) ----------
__device__ __align__(256) __nv_bfloat16 g_fnh[N1 * PN * DD];  // normalized feats (bf16)
__device__ __align__(256) __nv_bfloat16 g_gnh[N2 * PN * DD];  // normalized nfeats (bf16)
__device__ float    g_fa2[N1 * PN];
__device__ float    g_gb2[N2 * PN];
__device__ unsigned g_minenc[N1 * N2 * PN];    // order-encoded min d2 over q
__device__ float    g_spatch[N1 * N2 * PN];
__device__ float    g_maxp[N1 * N2];
__device__ float    g_sp[N1 * PN];

// ---------------- helpers ----------------
__device__ __forceinline__ unsigned enc_f(float f) {
    unsigned u = __float_as_uint(f);
    return (u & 0x80000000u) ? ~u : (u | 0x80000000u);
}
__device__ __forceinline__ float dec_f(unsigned e) {
    unsigned u = (e & 0x80000000u) ? (e ^ 0x80000000u) : ~e;
    return __uint_as_float(u);
}
__device__ __forceinline__ uint32_t smem_u32(const void* p) {
    uint32_t a;
    asm("{ .reg .u64 t; cvta.to.shared.u64 t, %1; cvt.u32.u64 %0, t; }" : "=r"(a) : "l"(p));
    return a;
}
__device__ __forceinline__ void cp16(uint32_t dst, const void* src) {
    asm volatile("cp.async.cg.shared.global [%0], [%1], 16;" :: "r"(dst), "l"(src) : "memory");
}
__device__ __forceinline__ void cp_commit() {
    asm volatile("cp.async.commit_group;" ::: "memory");
}
__device__ __forceinline__ void cp_wait1() {
    asm volatile("cp.async.wait_group 1;" ::: "memory");
}
__device__ __forceinline__ void cp_wait0() {
    asm volatile("cp.async.wait_group 0;" ::: "memory");
}
__device__ __forceinline__ void ldsm_x4(unsigned& r0, unsigned& r1, unsigned& r2, unsigned& r3,
                                        uint32_t addr) {
    asm volatile("ldmatrix.sync.aligned.m8n8.x4.shared.b16 {%0,%1,%2,%3}, [%4];"
                 : "=r"(r0), "=r"(r1), "=r"(r2), "=r"(r3) : "r"(addr));
}
__device__ __forceinline__ void mma_bf16(float& c0, float& c1, float& c2, float& c3,
                                         unsigned a0, unsigned a1, unsigned a2, unsigned a3,
                                         unsigned b0, unsigned b1) {
    asm volatile(
        "mma.sync.aligned.m16n8k16.row.col.f32.bf16.bf16.f32 "
        "{%0,%1,%2,%3}, {%4,%5,%6,%7}, {%8,%9}, {%0,%1,%2,%3};\n"
        : "+f"(c0), "+f"(c1), "+f"(c2), "+f"(c3)
        : "r"(a0), "r"(a1), "r"(a2), "r"(a3), "r"(b0), "r"(b1));
}

// ---------------- kernel 1: row-normalize -> bf16 + sum-of-squares ----------
__global__ void normalize_kernel(const float* __restrict__ in, int which) {
    int row = blockIdx.x;
    const float* x = in + (size_t)row * DD;
    __nv_bfloat16* y = (which ? g_gnh : g_fnh) + (size_t)row * DD;
    float* sq = (which ? g_gb2 : g_fa2);

    __shared__ float red[256];
    int t = threadIdx.x;

    float s = 0.f;
    for (int i = t; i < DD; i += 256) { float v = x[i]; s += v * v; }
    red[t] = s; __syncthreads();
    for (int o = 128; o > 0; o >>= 1) { if (t < o) red[t] += red[t + o]; __syncthreads(); }
    float nrm = sqrtf(red[0]);
    __syncthreads();

    float s2 = 0.f;
    for (int i = t; i < DD; i += 256) {
        float v = x[i] / nrm;
        y[i] = __float2bfloat16_rn(v);
        s2 += v * v;
    }
    red[t] = s2; __syncthreads();
    for (int o = 128; o > 0; o >>= 1) { if (t < o) red[t] += red[t + o]; __syncthreads(); }
    if (t == 0) sq[row] = red[0];
}

// ---------------- kernel 2: init min buffer ----------------
__global__ void init_min_kernel() {
    int i = blockIdx.x * blockDim.x + threadIdx.x;
    if (i < N1 * N2 * PN) g_minenc[i] = 0xFFFFFFFFu;
}

// ---------------- kernel 3: bf16 MMA GEMM + min-over-q epilogue ------------
// C[p,q] = f_n[p].g_m[q]; per-p min over q of (gb2[q] - 2C) -> atomicMin.
// 128x128 CTA tile, 64x32 warp tile (2 CTAs/SM), 3-stage cp.async pipeline,
// ldmatrix.x4 fragment loads (rows 80B-padded: conflict-free LDSM phases).
__global__ __launch_bounds__(256) void gemm_min_kernel() {
    extern __shared__ char smem[];
    const uint32_t sb = smem_u32(smem);

    const int t = threadIdx.x;
    const int lane = t & 31, w = t >> 5;
    const int wm = w >> 2;      // 0..1 -> 64 rows each
    const int wn = w & 3;       // 0..3 -> 32 cols each
    const int g8 = lane >> 2;   // 0..7 (mma row/col group)
    const int qd = lane & 3;    // 0..3
    const int seg = lane >> 3;  // 0..3 (ldmatrix segment)
    const int l7 = lane & 7;

    const int nI = blockIdx.z >> 3, mI = blockIdx.z & 7;
    const int p0 = blockIdx.y * BM, q0 = blockIdx.x * BN;

    const __nv_bfloat16* __restrict__ Fp = g_fnh + ((size_t)nI * PN + p0) * DD;
    const __nv_bfloat16* __restrict__ Gp = g_gnh + ((size_t)mI * PN + q0) * DD;

    // loader mapping (per chunk BK=32 = 64B/row): 2 thr/row, 32B each (2x cp16)
    const int ra = t >> 1, hf = t & 1;
    const char* gA = (const char*)(Fp + (size_t)ra * DD) + hf * 32;
    const char* gB = (const char*)(Gp + (size_t)ra * DD) + hf * 32;
    const uint32_t sA0 = sb + ra * ROWB + hf * 32;
    const uint32_t sB0 = sb + OF_Bm + ra * ROWB + hf * 32;

    // ldmatrix per-lane address offsets (relative to stage A/B base)
    // A i-tile (16x16): seg0 rows 0-7 @k0, seg1 rows 8-15 @k0, seg2 rows 0-7 @k8, seg3 rows 8-15 @k8
    const uint32_t aoff = (uint32_t)(wm * 64 + (seg & 1) * 8 + l7) * ROWB + ((seg >> 1) * 8) * 2;
    // B x4 covers 2 n-tiles: seg0 q0-7 @k0, seg1 q0-7 @k8, seg2 q8-15 @k0, seg3 q8-15 @k8
    const uint32_t boff = (uint32_t)(wn * 32 + (seg >> 1) * 8 + l7) * ROWB + ((seg & 1) * 8) * 2;

    float acc[4][4][4];
#pragma unroll
    for (int i = 0; i < 4; i++)
#pragma unroll
        for (int j = 0; j < 4; j++)
#pragma unroll
            for (int c = 0; c < 4; c++) acc[i][j][c] = 0.f;

#define ISSUE(c)                                                     \
    do {                                                             \
        const uint32_t _st = ((c) % 3) * STAGE_BYTES;                \
        const char* _ga = gA + (c) * 64;                             \
        const char* _gb = gB + (c) * 64;                             \
        cp16(sA0 + _st, _ga);        cp16(sA0 + _st + 16, _ga + 16); \
        cp16(sB0 + _st, _gb);        cp16(sB0 + _st + 16, _gb + 16); \
        cp_commit();                                                 \
    } while (0)

    ISSUE(0);
    ISSUE(1);

    for (int c = 0; c < NCHUNK; c++) {
        if (c >= NCHUNK - 1) cp_wait0(); else cp_wait1();
        __syncthreads();

        const uint32_t st = (c % 3) * STAGE_BYTES;
        const uint32_t abase = sb + st + aoff;
        const uint32_t bbase = sb + st + OF_Bm + boff;

        if (c + 2 < NCHUNK) ISSUE(c + 2);   // overlaps with compute below

#pragma unroll
        for (int kk = 0; kk < BK; kk += 16) {
            unsigned b01[4], b23[4];
            ldsm_x4(b01[0], b01[1], b01[2], b01[3], bbase + kk * 2);           // n-tiles 0,1
            ldsm_x4(b23[0], b23[1], b23[2], b23[3], bbase + 1280 + kk * 2);    // n-tiles 2,3
#pragma unroll
            for (int i = 0; i < 4; i++) {
                unsigned a0, a1, a2, a3;
                ldsm_x4(a0, a1, a2, a3, abase + i * 1280 + kk * 2);
                mma_bf16(acc[i][0][0], acc[i][0][1], acc[i][0][2], acc[i][0][3],
                         a0, a1, a2, a3, b01[0], b01[1]);
                mma_bf16(acc[i][1][0], acc[i][1][1], acc[i][1][2], acc[i][1][3],
                         a0, a1, a2, a3, b01[2], b01[3]);
                mma_bf16(acc[i][2][0], acc[i][2][1], acc[i][2][2], acc[i][2][3],
                         a0, a1, a2, a3, b23[0], b23[1]);
                mma_bf16(acc[i][3][0], acc[i][3][1], acc[i][3][2], acc[i][3][3],
                         a0, a1, a2, a3, b23[2], b23[3]);
            }
        }
        __syncthreads();
    }
#undef ISSUE

    // ---------------- epilogue: min over q of (gb2[q] - 2*C[p,q]) ----------
    const float* __restrict__ gb2p = g_gb2 + mI * PN + q0;
    float gbv[4][2];
#pragma unroll
    for (int j = 0; j < 4; j++) {
        const int cidx = wn * 32 + j * 8 + qd * 2;
        gbv[j][0] = gb2p[cidx];
        gbv[j][1] = gb2p[cidx + 1];
    }

    float (*red)[4] = (float (*)[4])smem;  // [128 rows][4 wn]

#pragma unroll
    for (int i = 0; i < 4; i++) {
        float mn_lo = FLT_BIG, mn_hi = FLT_BIG;
#pragma unroll
        for (int j = 0; j < 4; j++) {
            mn_lo = fminf(mn_lo, gbv[j][0] - 2.f * acc[i][j][0]);
            mn_lo = fminf(mn_lo, gbv[j][1] - 2.f * acc[i][j][1]);
            mn_hi = fminf(mn_hi, gbv[j][0] - 2.f * acc[i][j][2]);
            mn_hi = fminf(mn_hi, gbv[j][1] - 2.f * acc[i][j][3]);
        }
#pragma unroll
        for (int o = 1; o < 4; o <<= 1) {
            mn_lo = fminf(mn_lo, __shfl_xor_sync(0xFFFFFFFFu, mn_lo, o));
            mn_hi = fminf(mn_hi, __shfl_xor_sync(0xFFFFFFFFu, mn_hi, o));
        }
        if (qd == 0) {
            red[wm * 64 + i * 16 + g8][wn]     = mn_lo;
            red[wm * 64 + i * 16 + g8 + 8][wn] = mn_hi;
        }
    }
    __syncthreads();

    if (t < BM) {
        const float mn = fminf(fminf(red[t][0], red[t][1]), fminf(red[t][2], red[t][3]));
        const float d2 = g_fa2[nI * PN + p0 + t] + mn;
        atomicMin(&g_minenc[((nI << 3) + mI) * PN + p0 + t], enc_f(d2));
    }
}

// ---------------- kernel 4: scores_patch + max over p ----------------
__global__ void patch_kernel() {
    const int nm = blockIdx.x;
    __shared__ float red[256];
    const int t = threadIdx.x;
    float mx = 0.f;
    for (int p = t; p < PN; p += 256) {
        const float d2 = dec_f(g_minenc[nm * PN + p]);
        const float s = 0.5f * sqrtf(fmaxf(d2, 0.f));
        g_spatch[nm * PN + p] = s;
        mx = fmaxf(mx, s);
    }
    red[t] = mx; __syncthreads();
    for (int o = 128; o > 0; o >>= 1) { if (t < o) red[t] = fmaxf(red[t], red[t + o]); __syncthreads(); }
    if (t == 0) g_maxp[nm] = red[0];
}

// ---------------- kernel 5: mean over m (sp) + scores ----------------
__global__ void reduce_kernel(float* __restrict__ out) {
    const int idx = blockIdx.x * blockDim.x + threadIdx.x;
    if (idx >= N1 * PN) return;
    const int n = idx / PN;
    const int p = idx - n * PN;
    float s = 0.f;
#pragma unroll
    for (int m = 0; m < N2; m++) s += g_spatch[((n << 3) + m) * PN + p];
    g_sp[idx] = s * (1.0f / N2);
    if (idx < N1) {
        float sc = 0.f;
#pragma unroll
        for (int m = 0; m < N2; m++) sc += g_maxp[(idx << 3) + m];
        out[idx] = sc * (1.0f / N2);
    }
}

// ---------------- kernel 6: bilinear resize 32x32 -> 512x512 ----------------
__global__ void bilinear_kernel(float* __restrict__ out) {
    const int gid = blockIdx.x * blockDim.x + threadIdx.x;
    if (gid >= N1 * HH * WW) return;
    const int x = gid % WW;
    const int y = (gid / WW) % HH;
    const int n = gid / (WW * HH);

    const float sy = (y + 0.5f) * ((float)PHH / (float)HH) - 0.5f;
    const float sx = (x + 0.5f) * ((float)PWW / (float)WW) - 0.5f;
    const float y0f = floorf(sy), x0f = floorf(sx);
    const float wy = sy - y0f, wx = sx - x0f;
    const int y0 = min(max((int)y0f, 0), PHH - 1);
    const int y1 = min(max((int)y0f + 1, 0), PHH - 1);
    const int x0 = min(max((int)x0f, 0), PWW - 1);
    const int x1 = min(max((int)x0f + 1, 0), PWW - 1);

    const float* sp = g_sp + n * PN;
    const float v00 = sp[y0 * PWW + x0];
    const float v01 = sp[y0 * PWW + x1];
    const float v10 = sp[y1 * PWW + x0];
    const float v11 = sp[y1 * PWW + x1];
    const float top = v00 * (1.f - wx) + v01 * wx;
    const float bot = v10 * (1.f - wx) + v11 * wx;
    out[N1 + gid] = top * (1.f - wy) + bot * wy;
}

// ---------------- launch ----------------
extern "C" void kernel_launch(void* const* d_in, const int* in_sizes, int n_in,
                              void* d_out, int out_size) {
    const float* feats  = (const float*)d_in[0];
    const float* nfeats = (const float*)d_in[1];
    float* out = (float*)d_out;
    (void)in_sizes; (void)n_in; (void)out_size;

    cudaFuncSetAttribute(gemm_min_kernel,
                         cudaFuncAttributeMaxDynamicSharedMemorySize, SMEM_TOTAL);

    normalize_kernel<<<N1 * PN, 256>>>(feats, 0);
    normalize_kernel<<<N2 * PN, 256>>>(nfeats, 1);
    init_min_kernel<<<(N1 * N2 * PN + 255) / 256, 256>>>();
    gemm_min_kernel<<<dim3(PN / BN, PN / BM, N1 * N2), 256, SMEM_TOTAL>>>();
    patch_kernel<<<N1 * N2, 256>>>();
    reduce_kernel<<<(N1 * PN + 255) / 256, 256>>>(out);
    bilinear_kernel<<<(N1 * HH * WW + 255) / 256, 256>>>(out);
}